// round 17
// baseline (speedup 1.0000x reference)
#include <cuda_runtime.h>
#include <cuda_fp16.h>
#include <cstdint>

// out[b,o] = sum_i tanh(x[b,i]*t) * W[o,i],  W = sum_p coef[o,i,p]
// B=131072, I=O=128. fp32 in/out.
//
// mma.sync.m16n8k16 fp16 (fp32 accum), fp16 W (rel_err ~2.7e-4).
// Single fused kernel: blocks 0..63 compute B fragments (prep), release via
// acquire/release flag; consumers read g_BF with COHERENT loads (R16 bug was
// __ldg = non-coherent, exempt from acquire ordering).

static constexpr int IDIM = 128;
static constexpr int ODIM = 128;
static constexpr int TILE_M = 32;
static constexpr int PREP_BLOCKS = 64;

// B fragments, paired layout: block (kt, nt2) of 32 lanes x uint4 =
// [ntg=2*nt2 reg0, reg1, ntg=2*nt2+1 reg0, reg1]. 32KB, L2-hot.
__device__ uint32_t g_BF[8 * 8 * 32 * 4];
__device__ int g_ready;   // release flag: g_BF fully written
__device__ int g_done;    // prep blocks completed
__device__ int g_exit;    // CTAs exited (for self-reset)

// ---------------------------------------------------------------------------
// 5-op tanh: tanh(v*t) = 1 - 2/(e^{2vt}+1), e via ex2.approx. Clamp-free.
// ---------------------------------------------------------------------------
__device__ __forceinline__ float tanh_fast(float v, float c) {
    float e, r;
    asm("ex2.approx.f32 %0, %1;" : "=f"(e) : "f"(v * c));
    asm("rcp.approx.f32 %0, %1;" : "=f"(r) : "f"(e + 1.f));
    return fmaf(-2.f, r, 1.f);
}

__device__ __forceinline__ uint32_t pack_h2(float a, float b) {
    __half2 h = __floats2half2_rn(a, b);
    return *reinterpret_cast<uint32_t*>(&h);
}

#define MMA16816(d0, d1, d2, d3, a0, a1, a2, a3, b0, b1)                      \
    asm volatile(                                                             \
        "mma.sync.aligned.m16n8k16.row.col.f32.f16.f16.f32 "                  \
        "{%0,%1,%2,%3}, {%4,%5,%6,%7}, {%8,%9}, {%0,%1,%2,%3};"               \
        : "+f"(d0), "+f"(d1), "+f"(d2), "+f"(d3)                              \
        : "r"(a0), "r"(a1), "r"(a2), "r"(a3), "r"(b0), "r"(b1))

#define LDMATRIX_X4(a0, a1, a2, a3, addr)                                     \
    asm volatile(                                                             \
        "ldmatrix.sync.aligned.m8n8.x4.shared.b16 {%0,%1,%2,%3}, [%4];"       \
        : "=r"(a0), "=r"(a1), "=r"(a2), "=r"(a3) : "r"(addr))

// Coherent 16B global load (participates in acquire/release ordering).
#define LDG_COHERENT_16(v, ptr)                                               \
    asm volatile("ld.global.v4.b32 {%0,%1,%2,%3}, [%4];"                      \
                 : "=r"((v).x), "=r"((v).y), "=r"((v).z), "=r"((v).w)         \
                 : "l"(ptr) : "memory")

// SMEM: 8KB. Phase 1: A tile 32 rows x 256B (XOR-16B swizzle).
// Epilogue: reused as 16 rows x 512B fp32 staging (XOR-32B swizzle), 2 halves.
static constexpr int SMEM_TOTAL = 8192;

// ---------------------------------------------------------------------------
__global__ __launch_bounds__(128, 8) void fused_tanh_gemm_kernel(
    const float* __restrict__ x, const float* __restrict__ coef,
    const float* __restrict__ tanh_range, float* __restrict__ out)
{
    extern __shared__ __align__(16) char smem[];
    uint32_t sbase;
    asm("{ .reg .u64 t; cvta.to.shared.u64 t, %1; cvt.u32.u64 %0, t; }"
        : "=r"(sbase) : "l"(smem));

    const int tid = threadIdx.x;
    const int lane = tid & 31;
    const int wid = tid >> 5;          // 0..3 = ngroup
    const size_t rowBase = (size_t)blockIdx.x * TILE_M;

    // ---- prep (blocks 0..63): W = sum_p coef -> fp16 -> B fragments ----
    if (blockIdx.x < PREP_BLOCKS) {
        int idx = blockIdx.x * 128 + tid;          // 0..8191
        int nt = idx >> 9;
        int kt = (idx >> 6) & 7;
        int plane = (idx >> 1) & 31;
        int reg = idx & 1;
        int n = nt * 8 + (plane >> 2);
        int k = kt * 16 + (plane & 3) * 2 + reg * 8;

        const float4* c0 = reinterpret_cast<const float4*>(coef + ((size_t)n * 128 + k) * 16);
        const float4* c1 = reinterpret_cast<const float4*>(coef + ((size_t)n * 128 + k + 1) * 16);
        float4 v[8];
#pragma unroll
        for (int j = 0; j < 4; j++) v[j] = c0[j];
#pragma unroll
        for (int j = 0; j < 4; j++) v[4 + j] = c1[j];
        float s0 = 0.f, s1 = 0.f;
#pragma unroll
        for (int j = 0; j < 4; j++) s0 += (v[j].x + v[j].y) + (v[j].z + v[j].w);
#pragma unroll
        for (int j = 0; j < 4; j++) s1 += (v[4 + j].x + v[4 + j].y) + (v[4 + j].z + v[4 + j].w);
        __half2 hh = __floats2half2_rn(s0, s1);
        int pos = ((kt * 8 + (nt >> 1)) * 32 + plane) * 4 + (nt & 1) * 2 + reg;
        g_BF[pos] = *reinterpret_cast<uint32_t*>(&hh);

        __threadfence();
        __syncthreads();
        if (tid == 0) {
            int o = atomicAdd(&g_done, 1);
            if (o == PREP_BLOCKS - 1) {
                asm volatile("st.global.release.gpu.b32 [%0], %1;"
                             :: "l"(&g_ready), "r"(1) : "memory");
            }
        }
    }

    // ---- stage 1: front-batched coalesced loads + tanh + swizzled STS ----
    {
        const float c = __ldg(tanh_range) * 2.885390082f;   // 2*log2(e)*t
        const float4* x4 = reinterpret_cast<const float4*>(x + rowBase * IDIM);
        float4 v[8];
#pragma unroll
        for (int p = 0; p < 8; p++)
            v[p] = __ldcs(&x4[(wid * 8 + p) * 32 + lane]);
#pragma unroll
        for (int p = 0; p < 8; p++) {
            int row = wid * 8 + p;
            uint2 hp;
            hp.x = pack_h2(tanh_fast(v[p].x, c), tanh_fast(v[p].y, c));
            hp.y = pack_h2(tanh_fast(v[p].z, c), tanh_fast(v[p].w, c));
            uint32_t byte = (uint32_t)row * 256 + ((lane * 8) ^ ((row & 7) << 4));
            *reinterpret_cast<uint2*>(smem + byte) = hp;
        }
    }

    // ---- wait for g_BF (acquire; invalidates L1 so weak loads see fresh data)
    if (tid == 0) {
        int r;
        do {
            asm volatile("ld.global.acquire.gpu.b32 %0, [%1];"
                         : "=r"(r) : "l"(&g_ready) : "memory");
            if (r == 0) __nanosleep(64);
        } while (r == 0);
    }
    __syncthreads();

    // ---- stage 2: MMA (B via coherent loads — NOT __ldg) ----
    float acc[2][4][4];
#pragma unroll
    for (int a = 0; a < 2; a++)
#pragma unroll
        for (int b = 0; b < 4; b++)
#pragma unroll
            for (int cc = 0; cc < 4; cc++) acc[a][b][cc] = 0.f;

    const int lrow = ((lane >> 3) & 1) * 8 + (lane & 7);
    const uint32_t chi = (uint32_t)((lane >> 4) << 4);
    const uint32_t sw = (uint32_t)((lane & 7) << 4);
    const uint4* gb = reinterpret_cast<const uint4*>(g_BF);

#pragma unroll
    for (int kt = 0; kt < 8; kt++) {
        uint32_t a0[2], a1[2], a2[2], a3[2];
#pragma unroll
        for (int mt = 0; mt < 2; mt++) {
            int r = mt * 16 + lrow;
            uint32_t addr = sbase + (uint32_t)r * 256 + (((uint32_t)kt * 32 + chi) ^ sw);
            LDMATRIX_X4(a0[mt], a1[mt], a2[mt], a3[mt], addr);
        }
#pragma unroll
        for (int j = 0; j < 2; j++) {               // nt pair j -> nt = 2j, 2j+1
            uint4 q;
            LDG_COHERENT_16(q, &gb[(size_t)((kt * 8 + wid * 2 + j) * 32 + lane)]);
#pragma unroll
            for (int mt = 0; mt < 2; mt++) {
                MMA16816(acc[mt][2 * j][0], acc[mt][2 * j][1],
                         acc[mt][2 * j][2], acc[mt][2 * j][3],
                         a0[mt], a1[mt], a2[mt], a3[mt], q.x, q.y);
                MMA16816(acc[mt][2 * j + 1][0], acc[mt][2 * j + 1][1],
                         acc[mt][2 * j + 1][2], acc[mt][2 * j + 1][3],
                         a0[mt], a1[mt], a2[mt], a3[mt], q.z, q.w);
            }
        }
    }

    // ---- epilogue: two 16-row halves restaged through the 8KB A region ----
    __syncthreads();   // all ldmatrix A-tile reads complete
#pragma unroll
    for (int h = 0; h < 2; h++) {
#pragma unroll
        for (int half8 = 0; half8 < 2; half8++) {
            int slot = (lane >> 2) + half8 * 8;    // 0..15
#pragma unroll
            for (int nt = 0; nt < 4; nt++) {
                uint32_t cbyte = (uint32_t)(wid * 32 + nt * 8 + ((lane & 3) << 1)) * 4;
                *reinterpret_cast<float2*>(
                    smem + slot * 512 + (cbyte ^ ((uint32_t)(slot & 7) << 5)))
                    = make_float2(acc[h][nt][half8 * 2], acc[h][nt][half8 * 2 + 1]);
            }
        }
        __syncthreads();

        // coalesced STG of 16 staged rows (16 x 512B = 8KB)
        float* obase = out + (rowBase + (size_t)h * 16) * ODIM;
#pragma unroll
        for (int it = 0; it < 4; it++) {
            int idx = tid + it * 128;
            int slot = idx >> 5;                   // 0..15
            int u = idx & 31;
            uint32_t logical = (uint32_t)u * 16;
            uint32_t swz = logical ^ ((uint32_t)(slot & 7) << 5);
            uint4 val = *reinterpret_cast<const uint4*>(smem + slot * 512 + swz);
            __stcs(reinterpret_cast<uint4*>(
                       reinterpret_cast<char*>(obase + (size_t)slot * ODIM) + logical),
                   val);
        }
        if (h == 0) __syncthreads();   // half-0 reads done before half-1 staging
    }

    // ---- self-reset for graph replay: last exiting CTA zeroes the flags ----
    __syncthreads();
    if (tid == 0) {
        int o = atomicAdd(&g_exit, 1);
        if (o == (int)gridDim.x - 1) {
            g_done = 0;
            g_ready = 0;
            g_exit = 0;
            __threadfence();
        }
    }
}

// ---------------------------------------------------------------------------
extern "C" void kernel_launch(void* const* d_in, const int* in_sizes, int n_in,
                              void* d_out, int out_size) {
    const float* x = (const float*)d_in[0];
    const float* coef = (const float*)d_in[1];
    const float* tr = (const float*)d_in[2];
    float* out = (float*)d_out;

    cudaFuncSetAttribute(fused_tanh_gemm_kernel,
                         cudaFuncAttributeMaxDynamicSharedMemorySize, SMEM_TOTAL);

    int rows = in_sizes[0] / IDIM;     // 131072
    int grid = rows / TILE_M;          // 4096

    fused_tanh_gemm_kernel<<<grid, 128, SMEM_TOTAL>>>(x, coef, tr, out);
}